// round 8
// baseline (speedup 1.0000x reference)
#include <cuda_runtime.h>
#include <cuda_fp16.h>
#include <cstdint>

// ---------------------------------------------------------------------------
// GCN link prediction:
//   h1 = relu(agg(x  @ W1) + b1)
//   h2 = relu(agg(h1 @ W2) + b2)
//   z  =      agg(h2 @ W3) + b3
//   out[l] = dot(z[eli0[l]], z[eli1[l]])
// agg(Y)[n] = sum_{e: dst[e]==n} Y[src[e]]   (CSR-based, rebuilt every call)
// GEMMs: fp16 mma.sync m16n8k16, fp32 accum.
// Chunked agg->gemm pipelining across two streams:
//   agg1 chunk c (main) -> gemm2 chunk c (side, writes g_Yh2)
//   agg2 chunk c (main) -> gemm3 chunk c (side)
// ---------------------------------------------------------------------------

namespace {
constexpr int NN   = 20000;
constexpr int EE   = 320000;
constexpr int LL   = 100000;
constexpr int DIN  = 512;
constexpr int DHID = 512;
constexpr int DOUT = 256;

constexpr int NCHK = 4;
// chunk boundaries in units of 128-row blocks: 40,40,40,37 (157 total)
constexpr int CHK_BLK0[NCHK] = {0, 40, 80, 120};
constexpr int CHK_BLKS[NCHK] = {40, 40, 40, 37};
constexpr int CHK_N0[NCHK]   = {0, 5120, 10240, 15360};
constexpr int CHK_NN[NCHK]   = {5120, 5120, 5120, 4640};
}

__device__ __half g_Yh  [NN * DHID];   // layer-1 GEMM output
__device__ __half g_Yh2 [NN * DHID];   // layer-2 GEMM output (separate: WAR)
__device__ __half g_Hh  [NN * DHID];   // aggregated hidden (h1 then h2)
__device__ __half g_Y3h [NN * DOUT];
__device__ __half g_Zh  [NN * DOUT];
__device__ __half g_W1h[DIN * DHID];
__device__ __half g_W2h[DHID * DHID];
__device__ __half g_W3h[DHID * DOUT];
__device__ __align__(16) int g_rowptr[NN + 4];
__device__ __align__(16) int g_pos[NN];
__device__ int g_srcs[EE];

// ---------------------------------------------------------------------------
// Weight conversion fp32 -> fp16
// ---------------------------------------------------------------------------

__global__ void k_cvt_w(const float* __restrict__ W1, const float* __restrict__ W2,
                        const float* __restrict__ W3) {
    int i = blockIdx.x * blockDim.x + threadIdx.x;   // float4 index
    const float* src; __half* dst; int off;
    if (i < 65536)       { src = W1; dst = g_W1h; off = i; }
    else if (i < 131072) { src = W2; dst = g_W2h; off = i - 65536; }
    else if (i < 163840) { src = W3; dst = g_W3h; off = i - 131072; }
    else return;
    float4 v = ((const float4*)src)[off];
    uint2 u;
    *(__half2*)&u.x = __floats2half2_rn(v.x, v.y);
    *(__half2*)&u.y = __floats2half2_rn(v.z, v.w);
    ((uint2*)dst)[off] = u;
}

// ---------------------------------------------------------------------------
// CSR construction
// ---------------------------------------------------------------------------

__global__ void k_zero_deg() {
    int i = blockIdx.x * blockDim.x + threadIdx.x;
    if (i < NN / 4) ((int4*)g_pos)[i] = make_int4(0, 0, 0, 0);
}

__global__ void k_hist(const int* __restrict__ dst) {
    int e = blockIdx.x * blockDim.x + threadIdx.x;
    if (e < EE) atomicAdd(&g_pos[dst[e]], 1);
}

__global__ void k_scan() {
    __shared__ int wsum[32];
    const int tid  = threadIdx.x;
    const int lane = tid & 31;
    const int wid  = tid >> 5;

    int4 v[5];
    int local = 0;
    const bool act = tid < 1000;
    if (act) {
        const int4* p = (const int4*)g_pos + tid * 5;
        #pragma unroll
        for (int i = 0; i < 5; i++) {
            v[i] = p[i];
            local += v[i].x + v[i].y + v[i].z + v[i].w;
        }
    }

    int inc = local;
    #pragma unroll
    for (int o = 1; o < 32; o <<= 1) {
        int t = __shfl_up_sync(0xffffffffu, inc, o);
        if (lane >= o) inc += t;
    }
    if (lane == 31) wsum[wid] = inc;
    __syncthreads();

    if (wid == 0) {
        int w = wsum[lane];
        #pragma unroll
        for (int o = 1; o < 32; o <<= 1) {
            int t = __shfl_up_sync(0xffffffffu, w, o);
            if (lane >= o) w += t;
        }
        wsum[lane] = w;
    }
    __syncthreads();

    int run = (wid ? wsum[wid - 1] : 0) + (inc - local);
    if (act) {
        int4* rp = (int4*)g_rowptr + tid * 5;
        int4* pp = (int4*)g_pos + tid * 5;
        #pragma unroll
        for (int i = 0; i < 5; i++) {
            int4 d = v[i];
            int4 r;
            r.x = run; run += d.x;
            r.y = run; run += d.y;
            r.z = run; run += d.z;
            r.w = run; run += d.w;
            rp[i] = r;
            pp[i] = r;
        }
    }
    if (tid == 0) g_rowptr[NN] = wsum[31];
}

__global__ void k_scatter(const int* __restrict__ src, const int* __restrict__ dst) {
    int e = blockIdx.x * blockDim.x + threadIdx.x;
    if (e < EE) {
        int idx = atomicAdd(&g_pos[dst[e]], 1);
        g_srcs[idx] = src[e];
    }
}

// ---------------------------------------------------------------------------
// mma/ldmatrix helpers
// ---------------------------------------------------------------------------

#define BM 128
#define BN 128
#define BK 32

__device__ __forceinline__ uint32_t smem_u32(const void* p) {
    return (uint32_t)__cvta_generic_to_shared(p);
}

__device__ __forceinline__ void ldm_x4(uint32_t* r, uint32_t addr) {
    asm volatile("ldmatrix.sync.aligned.m8n8.x4.shared.b16 {%0,%1,%2,%3}, [%4];"
                 : "=r"(r[0]), "=r"(r[1]), "=r"(r[2]), "=r"(r[3]) : "r"(addr));
}

__device__ __forceinline__ void ldm_x4_t(uint32_t* r, uint32_t addr) {
    asm volatile("ldmatrix.sync.aligned.m8n8.x4.trans.shared.b16 {%0,%1,%2,%3}, [%4];"
                 : "=r"(r[0]), "=r"(r[1]), "=r"(r[2]), "=r"(r[3]) : "r"(addr));
}

__device__ __forceinline__ void mma_f16(float* c, const uint32_t* a, const uint32_t* b) {
    asm volatile(
        "mma.sync.aligned.m16n8k16.row.col.f32.f16.f16.f32 "
        "{%0,%1,%2,%3}, {%4,%5,%6,%7}, {%8,%9}, {%0,%1,%2,%3};\n"
        : "+f"(c[0]), "+f"(c[1]), "+f"(c[2]), "+f"(c[3])
        : "r"(a[0]), "r"(a[1]), "r"(a[2]), "r"(a[3]), "r"(b[0]), "r"(b[1]));
}

// ---------------------------------------------------------------------------
// fp16 GEMM, register-staged double buffer. AHALF selects fp16 vs fp32 A.
// by0: block-row offset (for chunked launches).
// ---------------------------------------------------------------------------

template <int N, int K, bool AHALF>
__device__ __forceinline__ void gemm_f16_body(const void* __restrict__ Aptr,
                                              const __half* __restrict__ Bw,
                                              __half* __restrict__ C, int by0) {
    constexpr int M  = NN;
    constexpr int AS = BK + 8;
    constexpr int BS = BN + 8;
    __shared__ __half As[2][BM][AS];
    __shared__ __half Bs[2][BK][BS];

    const int tid  = threadIdx.x;
    const int bx   = blockIdx.x;
    const int by   = blockIdx.y + by0;
    const int wid  = tid >> 5;
    const int lane = tid & 31;
    const int gid  = lane >> 2;
    const int tig  = lane & 3;
    const int wm0  = (wid & 1) * 64;
    const int wn0  = (wid >> 1) * 32;

    float acc[4][4][4];
    #pragma unroll
    for (int i = 0; i < 4; i++)
        #pragma unroll
        for (int j = 0; j < 4; j++)
            #pragma unroll
            for (int q = 0; q < 4; q++) acc[i][j][q] = 0.0f;

    uint4  aH[2];
    float4 aF[4];
    uint4  bH[2];

    auto loadGlobal = [&](int k0) {
        if (AHALF) {
            const __half* Ah = (const __half*)Aptr;
            #pragma unroll
            for (int l = 0; l < 2; l++) {
                int fidx = tid + l * 256;
                int row = fidx >> 2, col8 = fidx & 3;
                int grow = by * BM + row;
                aH[l] = (grow < M)
                    ? *(const uint4*)(Ah + (size_t)grow * K + k0 + col8 * 8)
                    : make_uint4(0u, 0u, 0u, 0u);
            }
        } else {
            const float* Af = (const float*)Aptr;
            #pragma unroll
            for (int l = 0; l < 4; l++) {
                int fidx = tid + l * 256;
                int row = fidx >> 3, col4 = fidx & 7;
                int grow = by * BM + row;
                aF[l] = (grow < M)
                    ? *(const float4*)(Af + (size_t)grow * K + k0 + col4 * 4)
                    : make_float4(0.f, 0.f, 0.f, 0.f);
            }
        }
        #pragma unroll
        for (int l = 0; l < 2; l++) {
            int fidx = tid + l * 256;
            int row = fidx >> 4, col8 = fidx & 15;
            bH[l] = *(const uint4*)(Bw + (size_t)(k0 + row) * N + bx * BN + col8 * 8);
        }
    };

    auto storeSmem = [&](int buf) {
        if (AHALF) {
            #pragma unroll
            for (int l = 0; l < 2; l++) {
                int fidx = tid + l * 256;
                int row = fidx >> 2, col8 = fidx & 3;
                *(uint4*)&As[buf][row][col8 * 8] = aH[l];
            }
        } else {
            #pragma unroll
            for (int l = 0; l < 4; l++) {
                int fidx = tid + l * 256;
                int row = fidx >> 3, col4 = fidx & 7;
                uint2 u;
                *(__half2*)&u.x = __floats2half2_rn(aF[l].x, aF[l].y);
                *(__half2*)&u.y = __floats2half2_rn(aF[l].z, aF[l].w);
                *(uint2*)&As[buf][row][col4 * 4] = u;
            }
        }
        #pragma unroll
        for (int l = 0; l < 2; l++) {
            int fidx = tid + l * 256;
            int row = fidx >> 4, col8 = fidx & 15;
            *(uint4*)&Bs[buf][row][col8 * 8] = bH[l];
        }
    };

    loadGlobal(0);
    storeSmem(0);
    __syncthreads();

    constexpr int NT = K / BK;
    int cur = 0;
    for (int kt = 0; kt < NT; kt++) {
        if (kt + 1 < NT) loadGlobal((kt + 1) * BK);

        #pragma unroll
        for (int ks = 0; ks < 2; ks++) {
            const int kb = ks * 16;
            uint32_t af[4][4], bf[4][2];
            #pragma unroll
            for (int mi = 0; mi < 4; mi++) {
                int row = wm0 + mi * 16 + (lane & 15);
                int col = kb + ((lane >> 4) << 3);
                ldm_x4(af[mi], smem_u32(&As[cur][row][col]));
            }
            #pragma unroll
            for (int nh = 0; nh < 2; nh++) {
                int row = kb + (lane & 15);
                int col = wn0 + nh * 16 + ((lane >> 4) << 3);
                uint32_t r[4];
                ldm_x4_t(r, smem_u32(&Bs[cur][row][col]));
                bf[nh * 2][0] = r[0]; bf[nh * 2][1] = r[1];
                bf[nh * 2 + 1][0] = r[2]; bf[nh * 2 + 1][1] = r[3];
            }
            #pragma unroll
            for (int mi = 0; mi < 4; mi++)
                #pragma unroll
                for (int ni = 0; ni < 4; ni++)
                    mma_f16(acc[mi][ni], af[mi], bf[ni]);
        }

        if (kt + 1 < NT) {
            storeSmem(cur ^ 1);
            __syncthreads();
            cur ^= 1;
        }
    }

    #pragma unroll
    for (int mi = 0; mi < 4; mi++) {
        #pragma unroll
        for (int ni = 0; ni < 4; ni++) {
            int row0 = by * BM + wm0 + mi * 16 + gid;
            int col  = bx * BN + wn0 + ni * 8 + tig * 2;
            if (row0 < M)
                *(__half2*)(C + (size_t)row0 * N + col) =
                    __floats2half2_rn(acc[mi][ni][0], acc[mi][ni][1]);
            int row1 = row0 + 8;
            if (row1 < M)
                *(__half2*)(C + (size_t)row1 * N + col) =
                    __floats2half2_rn(acc[mi][ni][2], acc[mi][ni][3]);
        }
    }
}

__global__ void __launch_bounds__(256) k_gemm_l1(const float* __restrict__ A) {
    gemm_f16_body<DHID, DIN, false>(A, g_W1h, g_Yh, 0);
}
__global__ void __launch_bounds__(256) k_gemm_l2(int by0) {
    gemm_f16_body<DHID, DHID, true>(g_Hh, g_W2h, g_Yh2, by0);
}
__global__ void __launch_bounds__(256) k_gemm_l3(int by0) {
    gemm_f16_body<DOUT, DHID, true>(g_Hh, g_W3h, g_Y3h, by0);
}

// ---------------------------------------------------------------------------
// Aggregation (fp16 gather, fp32 accumulate, fp16 output)
// ---------------------------------------------------------------------------

__device__ __forceinline__ void acc8(float* a, uint4 v) {
    float2 f;
    f = __half22float2(*(__half2*)&v.x); a[0] += f.x; a[1] += f.y;
    f = __half22float2(*(__half2*)&v.y); a[2] += f.x; a[3] += f.y;
    f = __half22float2(*(__half2*)&v.z); a[4] += f.x; a[5] += f.y;
    f = __half22float2(*(__half2*)&v.w); a[6] += f.x; a[7] += f.y;
}

__device__ __forceinline__ void agg_hid_body(const uint4* __restrict__ Y,
                                             const float* __restrict__ bias,
                                             int n0) {
    const int n    = n0 + blockIdx.x * 2 + (threadIdx.x >> 6);
    const int lane = threadIdx.x & 63;
    const int c    = lane * 8;
    const int beg  = g_rowptr[n];
    const int end  = g_rowptr[n + 1];

    float acc[8];
    #pragma unroll
    for (int q = 0; q < 8; q++) acc[q] = 0.0f;

    int i = beg;
    for (; i + 3 < end; i += 4) {
        int s0 = g_srcs[i], s1 = g_srcs[i + 1], s2 = g_srcs[i + 2], s3 = g_srcs[i + 3];
        uint4 v0 = Y[(size_t)s0 * 64 + lane];
        uint4 v1 = Y[(size_t)s1 * 64 + lane];
        uint4 v2 = Y[(size_t)s2 * 64 + lane];
        uint4 v3 = Y[(size_t)s3 * 64 + lane];
        acc8(acc, v0); acc8(acc, v1); acc8(acc, v2); acc8(acc, v3);
    }
    for (; i < end; i++) {
        uint4 v = Y[(size_t)g_srcs[i] * 64 + lane];
        acc8(acc, v);
    }

    uint4 o;
    __half2* oh = (__half2*)&o;
    #pragma unroll
    for (int q = 0; q < 4; q++) {
        float r0 = fmaxf(acc[2 * q]     + bias[c + 2 * q],     0.0f);
        float r1 = fmaxf(acc[2 * q + 1] + bias[c + 2 * q + 1], 0.0f);
        oh[q] = __floats2half2_rn(r0, r1);
    }
    *((uint4*)(g_Hh + (size_t)n * DHID + c)) = o;
}

__global__ void __launch_bounds__(128) k_agg_h1(const float* __restrict__ bias, int n0) {
    agg_hid_body((const uint4*)g_Yh, bias, n0);
}
__global__ void __launch_bounds__(128) k_agg_h2(const float* __restrict__ bias, int n0) {
    agg_hid_body((const uint4*)g_Yh2, bias, n0);
}

__global__ void __launch_bounds__(128) k_agg_out(const float* __restrict__ bias) {
    const int n    = blockIdx.x * 4 + (threadIdx.x >> 5);
    const int lane = threadIdx.x & 31;
    const int c    = lane * 8;
    const int beg  = g_rowptr[n];
    const int end  = g_rowptr[n + 1];

    float acc[8];
    #pragma unroll
    for (int q = 0; q < 8; q++) acc[q] = 0.0f;

    const uint4* Y = (const uint4*)(g_Y3h);
    int i = beg;
    for (; i + 3 < end; i += 4) {
        int s0 = g_srcs[i], s1 = g_srcs[i + 1], s2 = g_srcs[i + 2], s3 = g_srcs[i + 3];
        uint4 v0 = Y[(size_t)s0 * 32 + lane];
        uint4 v1 = Y[(size_t)s1 * 32 + lane];
        uint4 v2 = Y[(size_t)s2 * 32 + lane];
        uint4 v3 = Y[(size_t)s3 * 32 + lane];
        acc8(acc, v0); acc8(acc, v1); acc8(acc, v2); acc8(acc, v3);
    }
    for (; i < end; i++) {
        uint4 v = Y[(size_t)g_srcs[i] * 32 + lane];
        acc8(acc, v);
    }

    uint4 o;
    __half2* oh = (__half2*)&o;
    #pragma unroll
    for (int q = 0; q < 4; q++)
        oh[q] = __floats2half2_rn(acc[2 * q] + bias[c + 2 * q],
                                  acc[2 * q + 1] + bias[c + 2 * q + 1]);
    *((uint4*)(g_Zh + (size_t)n * DOUT + c)) = o;
}

// ---------------------------------------------------------------------------
// Decode
// ---------------------------------------------------------------------------

__global__ void k_decode(const int* __restrict__ eli, float* __restrict__ out) {
    int g = blockIdx.x * blockDim.x + threadIdx.x;
    int w = g >> 5;
    int lane = g & 31;
    if (w >= LL) return;

    int a = eli[w];
    int b = eli[LL + w];
    uint4 va = ((const uint4*)(g_Zh + (size_t)a * DOUT))[lane];
    uint4 vb = ((const uint4*)(g_Zh + (size_t)b * DOUT))[lane];

    float s = 0.0f;
    const __half2* ha = (const __half2*)&va;
    const __half2* hb = (const __half2*)&vb;
    #pragma unroll
    for (int q = 0; q < 4; q++) {
        float2 fa = __half22float2(ha[q]);
        float2 fb = __half22float2(hb[q]);
        s += fa.x * fb.x + fa.y * fb.y;
    }

    #pragma unroll
    for (int o = 16; o; o >>= 1) s += __shfl_xor_sync(0xffffffffu, s, o);
    if (lane == 0) out[w] = s;
}

// ---------------------------------------------------------------------------
// Launch: fork CSR vs {cvt,gemm1}; chunked agg->gemm pipelining.
// ---------------------------------------------------------------------------

extern "C" void kernel_launch(void* const* d_in, const int* in_sizes, int n_in,
                              void* d_out, int out_size) {
    (void)in_sizes; (void)n_in; (void)out_size;
    const float* x   = (const float*)d_in[0];
    const int*   ei  = (const int*)  d_in[1];
    const int*   eli = (const int*)  d_in[2];
    const float* W1  = (const float*)d_in[3];
    const float* b1  = (const float*)d_in[4];
    const float* W2  = (const float*)d_in[5];
    const float* b2  = (const float*)d_in[6];
    const float* W3  = (const float*)d_in[7];
    const float* b3  = (const float*)d_in[8];
    float* out = (float*)d_out;

    const int* src = ei;
    const int* dst = ei + EE;

    static cudaStream_t s2 = nullptr;
    static cudaEvent_t evFork = nullptr, evL1 = nullptr, evG2 = nullptr, evG3 = nullptr;
    static cudaEvent_t evA[NCHK] = {}, evB[NCHK] = {};
    if (!s2) {
        cudaStreamCreateWithFlags(&s2, cudaStreamNonBlocking);
        cudaEventCreateWithFlags(&evFork, cudaEventDisableTiming);
        cudaEventCreateWithFlags(&evL1, cudaEventDisableTiming);
        cudaEventCreateWithFlags(&evG2, cudaEventDisableTiming);
        cudaEventCreateWithFlags(&evG3, cudaEventDisableTiming);
        for (int c = 0; c < NCHK; c++) {
            cudaEventCreateWithFlags(&evA[c], cudaEventDisableTiming);
            cudaEventCreateWithFlags(&evB[c], cudaEventDisableTiming);
        }
    }

    const dim3 gHID_full(DHID / BN, (NN + BM - 1) / BM);

    // Fork: side stream does weight conversion + layer-1 GEMM
    cudaEventRecord(evFork, 0);
    cudaStreamWaitEvent(s2, evFork, 0);
    k_cvt_w<<<640, 256, 0, s2>>>(W1, W2, W3);
    k_gemm_l1<<<gHID_full, 256, 0, s2>>>(x);
    cudaEventRecord(evL1, s2);

    // Main stream: CSR build
    k_zero_deg<<<20, 256>>>();
    k_hist<<<(EE + 255) / 256, 256>>>(dst);
    k_scan<<<1, 1024>>>();
    k_scatter<<<(EE + 255) / 256, 256>>>(src, dst);

    // Join: agg1 needs CSR (main) + gemm1 (side)
    cudaStreamWaitEvent(0, evL1, 0);

    // agg1 chunks (main) -> gemm2 chunks (side, writes g_Yh2)
    for (int c = 0; c < NCHK; c++) {
        k_agg_h1<<<CHK_NN[c] / 2, 128>>>(b1, CHK_N0[c]);
        cudaEventRecord(evA[c], 0);
    }
    for (int c = 0; c < NCHK; c++) {
        cudaStreamWaitEvent(s2, evA[c], 0);
        k_gemm_l2<<<dim3(DHID / BN, CHK_BLKS[c]), 256, 0, s2>>>(CHK_BLK0[c]);
    }
    cudaEventRecord(evG2, s2);

    // agg2 chunks (main, after ALL gemm2) -> gemm3 chunks (side)
    cudaStreamWaitEvent(0, evG2, 0);
    for (int c = 0; c < NCHK; c++) {
        k_agg_h2<<<CHK_NN[c] / 2, 128>>>(b2, CHK_N0[c]);
        cudaEventRecord(evB[c], 0);
    }
    for (int c = 0; c < NCHK; c++) {
        cudaStreamWaitEvent(s2, evB[c], 0);
        k_gemm_l3<<<dim3(DOUT / BN, CHK_BLKS[c]), 256, 0, s2>>>(CHK_BLK0[c]);
    }
    cudaEventRecord(evG3, s2);

    // Tail: agg3 (needs all gemm3), decode
    cudaStreamWaitEvent(0, evG3, 0);
    k_agg_out<<<NN / 4, 128>>>(b3);
    k_decode<<<(LL * 32 + 255) / 256, 256>>>(eli, out);
}

// round 9
// speedup vs baseline: 1.1768x; 1.1768x over previous
#include <cuda_runtime.h>
#include <cuda_fp16.h>
#include <cstdint>

// ---------------------------------------------------------------------------
// GCN link prediction:
//   h1 = relu(agg(x  @ W1) + b1)
//   h2 = relu(agg(h1 @ W2) + b2)
//   z  =      agg(h2 @ W3) + b3
//   out[l] = dot(z[eli0[l]], z[eli1[l]])
// agg(Y)[n] = sum_{e: dst[e]==n} Y[src[e]]   (CSR-based, rebuilt every call)
// GEMMs: fp16 mma.sync m16n8k16, fp32 accum, register-staged double buffer.
// Fork: side stream {cvt W1, gemm1} vs main {cvt W2/W3, CSR build}.
// ---------------------------------------------------------------------------

namespace {
constexpr int NN   = 20000;
constexpr int EE   = 320000;
constexpr int LL   = 100000;
constexpr int DIN  = 512;
constexpr int DHID = 512;
constexpr int DOUT = 256;
}

__device__ __half g_Yh [NN * DHID];
__device__ __half g_Hh [NN * DHID];
__device__ __half g_Y3h[NN * DOUT];
__device__ __half g_Zh [NN * DOUT];
__device__ __half g_W1h[DIN * DHID];
__device__ __half g_W2h[DHID * DHID];
__device__ __half g_W3h[DHID * DOUT];
__device__ __align__(16) int g_rowptr[NN + 4];
__device__ __align__(16) int g_pos[NN];
__device__ int g_srcs[EE];

// ---------------------------------------------------------------------------
// Weight conversion fp32 -> fp16 (split: W1 on side stream, W2/W3 on main)
// ---------------------------------------------------------------------------

__global__ void k_cvt_w1(const float* __restrict__ W1) {
    int i = blockIdx.x * blockDim.x + threadIdx.x;   // float4 index, 65536 total
    if (i >= 65536) return;
    float4 v = ((const float4*)W1)[i];
    uint2 u;
    *(__half2*)&u.x = __floats2half2_rn(v.x, v.y);
    *(__half2*)&u.y = __floats2half2_rn(v.z, v.w);
    ((uint2*)g_W1h)[i] = u;
}

__global__ void k_cvt_w23(const float* __restrict__ W2, const float* __restrict__ W3) {
    int i = blockIdx.x * blockDim.x + threadIdx.x;   // float4 index
    const float* src; __half* dst; int off;
    if (i < 65536)       { src = W2; dst = g_W2h; off = i; }
    else if (i < 98304)  { src = W3; dst = g_W3h; off = i - 65536; }
    else return;
    float4 v = ((const float4*)src)[off];
    uint2 u;
    *(__half2*)&u.x = __floats2half2_rn(v.x, v.y);
    *(__half2*)&u.y = __floats2half2_rn(v.z, v.w);
    ((uint2*)dst)[off] = u;
}

// ---------------------------------------------------------------------------
// CSR construction
// ---------------------------------------------------------------------------

__global__ void k_zero_deg() {
    int i = blockIdx.x * blockDim.x + threadIdx.x;
    if (i < NN / 4) ((int4*)g_pos)[i] = make_int4(0, 0, 0, 0);
}

__global__ void k_hist(const int* __restrict__ dst) {
    int e = blockIdx.x * blockDim.x + threadIdx.x;
    if (e < EE) atomicAdd(&g_pos[dst[e]], 1);
}

// Shuffle-based scan: 1000 active threads x 20 counters (5 x int4 each).
__global__ void k_scan() {
    __shared__ int wsum[32];
    const int tid  = threadIdx.x;
    const int lane = tid & 31;
    const int wid  = tid >> 5;

    int4 v[5];
    int local = 0;
    const bool act = tid < 1000;
    if (act) {
        const int4* p = (const int4*)g_pos + tid * 5;
        #pragma unroll
        for (int i = 0; i < 5; i++) {
            v[i] = p[i];
            local += v[i].x + v[i].y + v[i].z + v[i].w;
        }
    }

    int inc = local;
    #pragma unroll
    for (int o = 1; o < 32; o <<= 1) {
        int t = __shfl_up_sync(0xffffffffu, inc, o);
        if (lane >= o) inc += t;
    }
    if (lane == 31) wsum[wid] = inc;
    __syncthreads();

    if (wid == 0) {
        int w = wsum[lane];
        #pragma unroll
        for (int o = 1; o < 32; o <<= 1) {
            int t = __shfl_up_sync(0xffffffffu, w, o);
            if (lane >= o) w += t;
        }
        wsum[lane] = w;
    }
    __syncthreads();

    int run = (wid ? wsum[wid - 1] : 0) + (inc - local);
    if (act) {
        int4* rp = (int4*)g_rowptr + tid * 5;
        int4* pp = (int4*)g_pos + tid * 5;
        #pragma unroll
        for (int i = 0; i < 5; i++) {
            int4 d = v[i];
            int4 r;
            r.x = run; run += d.x;
            r.y = run; run += d.y;
            r.z = run; run += d.z;
            r.w = run; run += d.w;
            rp[i] = r;
            pp[i] = r;
        }
    }
    if (tid == 0) g_rowptr[NN] = wsum[31];
}

__global__ void k_scatter(const int* __restrict__ src, const int* __restrict__ dst) {
    int e = blockIdx.x * blockDim.x + threadIdx.x;
    if (e < EE) {
        int idx = atomicAdd(&g_pos[dst[e]], 1);
        g_srcs[idx] = src[e];
    }
}

// ---------------------------------------------------------------------------
// mma/ldmatrix helpers
// ---------------------------------------------------------------------------

#define BM 128
#define BN 128
#define BK 32

__device__ __forceinline__ uint32_t smem_u32(const void* p) {
    return (uint32_t)__cvta_generic_to_shared(p);
}

__device__ __forceinline__ void ldm_x4(uint32_t* r, uint32_t addr) {
    asm volatile("ldmatrix.sync.aligned.m8n8.x4.shared.b16 {%0,%1,%2,%3}, [%4];"
                 : "=r"(r[0]), "=r"(r[1]), "=r"(r[2]), "=r"(r[3]) : "r"(addr));
}

__device__ __forceinline__ void ldm_x4_t(uint32_t* r, uint32_t addr) {
    asm volatile("ldmatrix.sync.aligned.m8n8.x4.trans.shared.b16 {%0,%1,%2,%3}, [%4];"
                 : "=r"(r[0]), "=r"(r[1]), "=r"(r[2]), "=r"(r[3]) : "r"(addr));
}

__device__ __forceinline__ void mma_f16(float* c, const uint32_t* a, const uint32_t* b) {
    asm volatile(
        "mma.sync.aligned.m16n8k16.row.col.f32.f16.f16.f32 "
        "{%0,%1,%2,%3}, {%4,%5,%6,%7}, {%8,%9}, {%0,%1,%2,%3};\n"
        : "+f"(c[0]), "+f"(c[1]), "+f"(c[2]), "+f"(c[3])
        : "r"(a[0]), "r"(a[1]), "r"(a[2]), "r"(a[3]), "r"(b[0]), "r"(b[1]));
}

// ---------------------------------------------------------------------------
// fp16 GEMM, register-staged double buffer. AHALF selects fp16 vs fp32 A.
// ---------------------------------------------------------------------------

template <int N, int K, bool AHALF>
__device__ __forceinline__ void gemm_f16_body(const void* __restrict__ Aptr,
                                              const __half* __restrict__ Bw,
                                              __half* __restrict__ C) {
    constexpr int M  = NN;
    constexpr int AS = BK + 8;
    constexpr int BS = BN + 8;
    __shared__ __half As[2][BM][AS];
    __shared__ __half Bs[2][BK][BS];

    const int tid  = threadIdx.x;
    const int bx   = blockIdx.x;
    const int by   = blockIdx.y;
    const int wid  = tid >> 5;
    const int lane = tid & 31;
    const int gid  = lane >> 2;
    const int tig  = lane & 3;
    const int wm0  = (wid & 1) * 64;
    const int wn0  = (wid >> 1) * 32;

    float acc[4][4][4];
    #pragma unroll
    for (int i = 0; i < 4; i++)
        #pragma unroll
        for (int j = 0; j < 4; j++)
            #pragma unroll
            for (int q = 0; q < 4; q++) acc[i][j][q] = 0.0f;

    uint4  aH[2];
    float4 aF[4];
    uint4  bH[2];

    auto loadGlobal = [&](int k0) {
        if (AHALF) {
            const __half* Ah = (const __half*)Aptr;
            #pragma unroll
            for (int l = 0; l < 2; l++) {
                int fidx = tid + l * 256;
                int row = fidx >> 2, col8 = fidx & 3;
                int grow = by * BM + row;
                aH[l] = (grow < M)
                    ? *(const uint4*)(Ah + (size_t)grow * K + k0 + col8 * 8)
                    : make_uint4(0u, 0u, 0u, 0u);
            }
        } else {
            const float* Af = (const float*)Aptr;
            #pragma unroll
            for (int l = 0; l < 4; l++) {
                int fidx = tid + l * 256;
                int row = fidx >> 3, col4 = fidx & 7;
                int grow = by * BM + row;
                aF[l] = (grow < M)
                    ? *(const float4*)(Af + (size_t)grow * K + k0 + col4 * 4)
                    : make_float4(0.f, 0.f, 0.f, 0.f);
            }
        }
        #pragma unroll
        for (int l = 0; l < 2; l++) {
            int fidx = tid + l * 256;
            int row = fidx >> 4, col8 = fidx & 15;
            bH[l] = *(const uint4*)(Bw + (size_t)(k0 + row) * N + bx * BN + col8 * 8);
        }
    };

    auto storeSmem = [&](int buf) {
        if (AHALF) {
            #pragma unroll
            for (int l = 0; l < 2; l++) {
                int fidx = tid + l * 256;
                int row = fidx >> 2, col8 = fidx & 3;
                *(uint4*)&As[buf][row][col8 * 8] = aH[l];
            }
        } else {
            #pragma unroll
            for (int l = 0; l < 4; l++) {
                int fidx = tid + l * 256;
                int row = fidx >> 3, col4 = fidx & 7;
                uint2 u;
                *(__half2*)&u.x = __floats2half2_rn(aF[l].x, aF[l].y);
                *(__half2*)&u.y = __floats2half2_rn(aF[l].z, aF[l].w);
                *(uint2*)&As[buf][row][col4 * 4] = u;
            }
        }
        #pragma unroll
        for (int l = 0; l < 2; l++) {
            int fidx = tid + l * 256;
            int row = fidx >> 4, col8 = fidx & 15;
            *(uint4*)&Bs[buf][row][col8 * 8] = bH[l];
        }
    };

    loadGlobal(0);
    storeSmem(0);
    __syncthreads();

    constexpr int NT = K / BK;
    int cur = 0;
    for (int kt = 0; kt < NT; kt++) {
        if (kt + 1 < NT) loadGlobal((kt + 1) * BK);

        #pragma unroll
        for (int ks = 0; ks < 2; ks++) {
            const int kb = ks * 16;
            uint32_t af[4][4], bf[4][2];
            #pragma unroll
            for (int mi = 0; mi < 4; mi++) {
                int row = wm0 + mi * 16 + (lane & 15);
                int col = kb + ((lane >> 4) << 3);
                ldm_x4(af[mi], smem_u32(&As[cur][row][col]));
            }
            #pragma unroll
            for (int nh = 0; nh < 2; nh++) {
                int row = kb + (lane & 15);
                int col = wn0 + nh * 16 + ((lane >> 4) << 3);
                uint32_t r[4];
                ldm_x4_t(r, smem_u32(&Bs[cur][row][col]));
                bf[nh * 2][0] = r[0]; bf[nh * 2][1] = r[1];
                bf[nh * 2 + 1][0] = r[2]; bf[nh * 2 + 1][1] = r[3];
            }
            #pragma unroll
            for (int mi = 0; mi < 4; mi++)
                #pragma unroll
                for (int ni = 0; ni < 4; ni++)
                    mma_f16(acc[mi][ni], af[mi], bf[ni]);
        }

        if (kt + 1 < NT) {
            storeSmem(cur ^ 1);
            __syncthreads();
            cur ^= 1;
        }
    }

    #pragma unroll
    for (int mi = 0; mi < 4; mi++) {
        #pragma unroll
        for (int ni = 0; ni < 4; ni++) {
            int row0 = by * BM + wm0 + mi * 16 + gid;
            int col  = bx * BN + wn0 + ni * 8 + tig * 2;
            if (row0 < M)
                *(__half2*)(C + (size_t)row0 * N + col) =
                    __floats2half2_rn(acc[mi][ni][0], acc[mi][ni][1]);
            int row1 = row0 + 8;
            if (row1 < M)
                *(__half2*)(C + (size_t)row1 * N + col) =
                    __floats2half2_rn(acc[mi][ni][2], acc[mi][ni][3]);
        }
    }
}

__global__ void __launch_bounds__(256) k_gemm_l1(const float* __restrict__ A) {
    gemm_f16_body<DHID, DIN, false>(A, g_W1h, g_Yh);
}
__global__ void __launch_bounds__(256) k_gemm_l2() {
    gemm_f16_body<DHID, DHID, true>(g_Hh, g_W2h, g_Yh);
}
__global__ void __launch_bounds__(256) k_gemm_l3() {
    gemm_f16_body<DOUT, DHID, true>(g_Hh, g_W3h, g_Y3h);
}

// ---------------------------------------------------------------------------
// Aggregation (fp16 gather, fp32 accumulate, fp16 output)
// ---------------------------------------------------------------------------

__device__ __forceinline__ void acc8(float* a, uint4 v) {
    float2 f;
    f = __half22float2(*(__half2*)&v.x); a[0] += f.x; a[1] += f.y;
    f = __half22float2(*(__half2*)&v.y); a[2] += f.x; a[3] += f.y;
    f = __half22float2(*(__half2*)&v.z); a[4] += f.x; a[5] += f.y;
    f = __half22float2(*(__half2*)&v.w); a[6] += f.x; a[7] += f.y;
}

__global__ void __launch_bounds__(128) k_agg_hid(const float* __restrict__ bias) {
    const int n    = blockIdx.x * 2 + (threadIdx.x >> 6);
    const int lane = threadIdx.x & 63;
    const int c    = lane * 8;
    const int beg  = g_rowptr[n];
    const int end  = g_rowptr[n + 1];

    float acc[8];
    #pragma unroll
    for (int q = 0; q < 8; q++) acc[q] = 0.0f;

    const uint4* Y = (const uint4*)(g_Yh);
    int i = beg;
    for (; i + 3 < end; i += 4) {
        int s0 = g_srcs[i], s1 = g_srcs[i + 1], s2 = g_srcs[i + 2], s3 = g_srcs[i + 3];
        uint4 v0 = Y[(size_t)s0 * 64 + lane];
        uint4 v1 = Y[(size_t)s1 * 64 + lane];
        uint4 v2 = Y[(size_t)s2 * 64 + lane];
        uint4 v3 = Y[(size_t)s3 * 64 + lane];
        acc8(acc, v0); acc8(acc, v1); acc8(acc, v2); acc8(acc, v3);
    }
    for (; i < end; i++) {
        uint4 v = Y[(size_t)g_srcs[i] * 64 + lane];
        acc8(acc, v);
    }

    uint4 o;
    __half2* oh = (__half2*)&o;
    #pragma unroll
    for (int q = 0; q < 4; q++) {
        float r0 = fmaxf(acc[2 * q]     + bias[c + 2 * q],     0.0f);
        float r1 = fmaxf(acc[2 * q + 1] + bias[c + 2 * q + 1], 0.0f);
        oh[q] = __floats2half2_rn(r0, r1);
    }
    *((uint4*)(g_Hh + (size_t)n * DHID + c)) = o;
}

__global__ void __launch_bounds__(128) k_agg_out(const float* __restrict__ bias) {
    const int n    = blockIdx.x * 4 + (threadIdx.x >> 5);
    const int lane = threadIdx.x & 31;
    const int c    = lane * 8;
    const int beg  = g_rowptr[n];
    const int end  = g_rowptr[n + 1];

    float acc[8];
    #pragma unroll
    for (int q = 0; q < 8; q++) acc[q] = 0.0f;

    const uint4* Y = (const uint4*)(g_Y3h);
    int i = beg;
    for (; i + 3 < end; i += 4) {
        int s0 = g_srcs[i], s1 = g_srcs[i + 1], s2 = g_srcs[i + 2], s3 = g_srcs[i + 3];
        uint4 v0 = Y[(size_t)s0 * 32 + lane];
        uint4 v1 = Y[(size_t)s1 * 32 + lane];
        uint4 v2 = Y[(size_t)s2 * 32 + lane];
        uint4 v3 = Y[(size_t)s3 * 32 + lane];
        acc8(acc, v0); acc8(acc, v1); acc8(acc, v2); acc8(acc, v3);
    }
    for (; i < end; i++) {
        uint4 v = Y[(size_t)g_srcs[i] * 32 + lane];
        acc8(acc, v);
    }

    uint4 o;
    __half2* oh = (__half2*)&o;
    #pragma unroll
    for (int q = 0; q < 4; q++)
        oh[q] = __floats2half2_rn(acc[2 * q] + bias[c + 2 * q],
                                  acc[2 * q + 1] + bias[c + 2 * q + 1]);
    *((uint4*)(g_Zh + (size_t)n * DOUT + c)) = o;
}

// ---------------------------------------------------------------------------
// Decode
// ---------------------------------------------------------------------------

__global__ void k_decode(const int* __restrict__ eli, float* __restrict__ out) {
    int g = blockIdx.x * blockDim.x + threadIdx.x;
    int w = g >> 5;
    int lane = g & 31;
    if (w >= LL) return;

    int a = eli[w];
    int b = eli[LL + w];
    uint4 va = ((const uint4*)(g_Zh + (size_t)a * DOUT))[lane];
    uint4 vb = ((const uint4*)(g_Zh + (size_t)b * DOUT))[lane];

    float s = 0.0f;
    const __half2* ha = (const __half2*)&va;
    const __half2* hb = (const __half2*)&vb;
    #pragma unroll
    for (int q = 0; q < 4; q++) {
        float2 fa = __half22float2(ha[q]);
        float2 fb = __half22float2(hb[q]);
        s += fa.x * fb.x + fa.y * fb.y;
    }

    #pragma unroll
    for (int o = 16; o; o >>= 1) s += __shfl_xor_sync(0xffffffffu, s, o);
    if (lane == 0) out[w] = s;
}

// ---------------------------------------------------------------------------
// Launch: side {cvt W1, gemm1} vs main {cvt W2/W3, CSR}, then serial chain.
// ---------------------------------------------------------------------------

extern "C" void kernel_launch(void* const* d_in, const int* in_sizes, int n_in,
                              void* d_out, int out_size) {
    (void)in_sizes; (void)n_in; (void)out_size;
    const float* x   = (const float*)d_in[0];
    const int*   ei  = (const int*)  d_in[1];
    const int*   eli = (const int*)  d_in[2];
    const float* W1  = (const float*)d_in[3];
    const float* b1  = (const float*)d_in[4];
    const float* W2  = (const float*)d_in[5];
    const float* b2  = (const float*)d_in[6];
    const float* W3  = (const float*)d_in[7];
    const float* b3  = (const float*)d_in[8];
    float* out = (float*)d_out;

    const int* src = ei;
    const int* dst = ei + EE;

    static cudaStream_t s2 = nullptr;
    static cudaEvent_t evFork = nullptr, evL1 = nullptr;
    if (!s2) {
        cudaStreamCreateWithFlags(&s2, cudaStreamNonBlocking);
        cudaEventCreateWithFlags(&evFork, cudaEventDisableTiming);
        cudaEventCreateWithFlags(&evL1, cudaEventDisableTiming);
    }

    const dim3 gHID(DHID / BN, (NN + BM - 1) / BM);
    const dim3 gOUT(DOUT / BN, (NN + BM - 1) / BM);

    // Fork: side stream converts W1 then runs layer-1 GEMM
    cudaEventRecord(evFork, 0);
    cudaStreamWaitEvent(s2, evFork, 0);
    k_cvt_w1<<<256, 256, 0, s2>>>(W1);
    k_gemm_l1<<<gHID, 256, 0, s2>>>(x);
    cudaEventRecord(evL1, s2);

    // Main stream: W2/W3 conversion + CSR build
    k_cvt_w23<<<384, 256>>>(W2, W3);
    k_zero_deg<<<20, 256>>>();
    k_hist<<<(EE + 255) / 256, 256>>>(dst);
    k_scan<<<1, 1024>>>();
    k_scatter<<<(EE + 255) / 256, 256>>>(src, dst);

    // Join: aggregation needs both CSR and layer-1 GEMM output
    cudaStreamWaitEvent(0, evL1, 0);

    k_agg_hid<<<NN / 2, 128>>>(b1);
    k_gemm_l2<<<gHID, 256>>>();
    k_agg_hid<<<NN / 2, 128>>>(b2);
    k_gemm_l3<<<gOUT, 256>>>();
    k_agg_out<<<NN / 4, 128>>>(b3);
    k_decode<<<(LL * 32 + 255) / 256, 256>>>(eli, out);
}

// round 11
// speedup vs baseline: 1.2111x; 1.0291x over previous
#include <cuda_runtime.h>
#include <cuda_fp16.h>
#include <cstdint>

// ---------------------------------------------------------------------------
// GCN link prediction:
//   h1 = relu(agg(x  @ W1) + b1)
//   h2 = relu(agg(h1 @ W2) + b2)
//   z  =      agg(h2 @ W3) + b3
//   out[l] = dot(z[eli0[l]], z[eli1[l]])
// agg(Y)[n] = sum_{e: dst[e]==n} Y[src[e]]   (CSR-based, rebuilt every call)
// GEMMs: fp16 mma.sync m16n8k16, fp32 accum (tcgen05 unavailable: harness
// targets sm_100, not sm_100a). Fork: side {cvt W1, gemm1} vs main {cvt
// W2/W3, CSR}. Decode: 8 threads/edge with deep load ILP.
// ---------------------------------------------------------------------------

namespace {
constexpr int NN   = 20000;
constexpr int EE   = 320000;
constexpr int LL   = 100000;
constexpr int DIN  = 512;
constexpr int DHID = 512;
constexpr int DOUT = 256;
}

__device__ __half g_Yh [NN * DHID];
__device__ __half g_Hh [NN * DHID];
__device__ __half g_Y3h[NN * DOUT];
__device__ __half g_Zh [NN * DOUT];
__device__ __half g_W1h[DIN * DHID];
__device__ __half g_W2h[DHID * DHID];
__device__ __half g_W3h[DHID * DOUT];
__device__ __align__(16) int g_rowptr[NN + 4];
__device__ __align__(16) int g_pos[NN];
__device__ int g_srcs[EE];

// ---------------------------------------------------------------------------
// Weight conversion fp32 -> fp16 (split: W1 on side stream, W2/W3 on main)
// ---------------------------------------------------------------------------

__global__ void k_cvt_w1(const float* __restrict__ W1) {
    int i = blockIdx.x * blockDim.x + threadIdx.x;
    if (i >= 65536) return;
    float4 v = ((const float4*)W1)[i];
    uint2 u;
    *(__half2*)&u.x = __floats2half2_rn(v.x, v.y);
    *(__half2*)&u.y = __floats2half2_rn(v.z, v.w);
    ((uint2*)g_W1h)[i] = u;
}

__global__ void k_cvt_w23(const float* __restrict__ W2, const float* __restrict__ W3) {
    int i = blockIdx.x * blockDim.x + threadIdx.x;
    const float* src; __half* dst; int off;
    if (i < 65536)       { src = W2; dst = g_W2h; off = i; }
    else if (i < 98304)  { src = W3; dst = g_W3h; off = i - 65536; }
    else return;
    float4 v = ((const float4*)src)[off];
    uint2 u;
    *(__half2*)&u.x = __floats2half2_rn(v.x, v.y);
    *(__half2*)&u.y = __floats2half2_rn(v.z, v.w);
    ((uint2*)dst)[off] = u;
}

// ---------------------------------------------------------------------------
// CSR construction
// ---------------------------------------------------------------------------

__global__ void k_hist(const int* __restrict__ dst) {
    int e = blockIdx.x * blockDim.x + threadIdx.x;
    if (e < EE) atomicAdd(&g_pos[dst[e]], 1);
}

// Shuffle-based scan: 1000 active threads x 20 counters (5 x int4 each).
__global__ void k_scan() {
    __shared__ int wsum[32];
    const int tid  = threadIdx.x;
    const int lane = tid & 31;
    const int wid  = tid >> 5;

    int4 v[5];
    int local = 0;
    const bool act = tid < 1000;
    if (act) {
        const int4* p = (const int4*)g_pos + tid * 5;
        #pragma unroll
        for (int i = 0; i < 5; i++) {
            v[i] = p[i];
            local += v[i].x + v[i].y + v[i].z + v[i].w;
        }
    }

    int inc = local;
    #pragma unroll
    for (int o = 1; o < 32; o <<= 1) {
        int t = __shfl_up_sync(0xffffffffu, inc, o);
        if (lane >= o) inc += t;
    }
    if (lane == 31) wsum[wid] = inc;
    __syncthreads();

    if (wid == 0) {
        int w = wsum[lane];
        #pragma unroll
        for (int o = 1; o < 32; o <<= 1) {
            int t = __shfl_up_sync(0xffffffffu, w, o);
            if (lane >= o) w += t;
        }
        wsum[lane] = w;
    }
    __syncthreads();

    int run = (wid ? wsum[wid - 1] : 0) + (inc - local);
    if (act) {
        int4* rp = (int4*)g_rowptr + tid * 5;
        int4* pp = (int4*)g_pos + tid * 5;
        #pragma unroll
        for (int i = 0; i < 5; i++) {
            int4 d = v[i];
            int4 r;
            r.x = run; run += d.x;
            r.y = run; run += d.y;
            r.z = run; run += d.z;
            r.w = run; run += d.w;
            rp[i] = r;
            pp[i] = r;
        }
    }
    if (tid == 0) g_rowptr[NN] = wsum[31];
}

__global__ void k_scatter(const int* __restrict__ src, const int* __restrict__ dst) {
    int e = blockIdx.x * blockDim.x + threadIdx.x;
    if (e < EE) {
        int idx = atomicAdd(&g_pos[dst[e]], 1);
        g_srcs[idx] = src[e];
    }
}

// ---------------------------------------------------------------------------
// mma/ldmatrix helpers
// ---------------------------------------------------------------------------

#define BM 128
#define BN 128
#define BK 32

__device__ __forceinline__ uint32_t smem_u32(const void* p) {
    return (uint32_t)__cvta_generic_to_shared(p);
}

__device__ __forceinline__ void ldm_x4(uint32_t* r, uint32_t addr) {
    asm volatile("ldmatrix.sync.aligned.m8n8.x4.shared.b16 {%0,%1,%2,%3}, [%4];"
                 : "=r"(r[0]), "=r"(r[1]), "=r"(r[2]), "=r"(r[3]) : "r"(addr));
}

__device__ __forceinline__ void ldm_x4_t(uint32_t* r, uint32_t addr) {
    asm volatile("ldmatrix.sync.aligned.m8n8.x4.trans.shared.b16 {%0,%1,%2,%3}, [%4];"
                 : "=r"(r[0]), "=r"(r[1]), "=r"(r[2]), "=r"(r[3]) : "r"(addr));
}

__device__ __forceinline__ void mma_f16(float* c, const uint32_t* a, const uint32_t* b) {
    asm volatile(
        "mma.sync.aligned.m16n8k16.row.col.f32.f16.f16.f32 "
        "{%0,%1,%2,%3}, {%4,%5,%6,%7}, {%8,%9}, {%0,%1,%2,%3};\n"
        : "+f"(c[0]), "+f"(c[1]), "+f"(c[2]), "+f"(c[3])
        : "r"(a[0]), "r"(a[1]), "r"(a[2]), "r"(a[3]), "r"(b[0]), "r"(b[1]));
}

// ---------------------------------------------------------------------------
// fp16 GEMM, register-staged double buffer. AHALF selects fp16 vs fp32 A.
// ---------------------------------------------------------------------------

template <int N, int K, bool AHALF>
__device__ __forceinline__ void gemm_f16_body(const void* __restrict__ Aptr,
                                              const __half* __restrict__ Bw,
                                              __half* __restrict__ C) {
    constexpr int M  = NN;
    constexpr int AS = BK + 8;
    constexpr int BS = BN + 8;
    __shared__ __half As[2][BM][AS];
    __shared__ __half Bs[2][BK][BS];

    const int tid  = threadIdx.x;
    const int bx   = blockIdx.x;
    const int by   = blockIdx.y;
    const int wid  = tid >> 5;
    const int lane = tid & 31;
    const int gid  = lane >> 2;
    const int tig  = lane & 3;
    const int wm0  = (wid & 1) * 64;
    const int wn0  = (wid >> 1) * 32;

    float acc[4][4][4];
    #pragma unroll
    for (int i = 0; i < 4; i++)
        #pragma unroll
        for (int j = 0; j < 4; j++)
            #pragma unroll
            for (int q = 0; q < 4; q++) acc[i][j][q] = 0.0f;

    uint4  aH[2];
    float4 aF[4];
    uint4  bH[2];

    auto loadGlobal = [&](int k0) {
        if (AHALF) {
            const __half* Ah = (const __half*)Aptr;
            #pragma unroll
            for (int l = 0; l < 2; l++) {
                int fidx = tid + l * 256;
                int row = fidx >> 2, col8 = fidx & 3;
                int grow = by * BM + row;
                aH[l] = (grow < M)
                    ? *(const uint4*)(Ah + (size_t)grow * K + k0 + col8 * 8)
                    : make_uint4(0u, 0u, 0u, 0u);
            }
        } else {
            const float* Af = (const float*)Aptr;
            #pragma unroll
            for (int l = 0; l < 4; l++) {
                int fidx = tid + l * 256;
                int row = fidx >> 3, col4 = fidx & 7;
                int grow = by * BM + row;
                aF[l] = (grow < M)
                    ? *(const float4*)(Af + (size_t)grow * K + k0 + col4 * 4)
                    : make_float4(0.f, 0.f, 0.f, 0.f);
            }
        }
        #pragma unroll
        for (int l = 0; l < 2; l++) {
            int fidx = tid + l * 256;
            int row = fidx >> 4, col8 = fidx & 15;
            bH[l] = *(const uint4*)(Bw + (size_t)(k0 + row) * N + bx * BN + col8 * 8);
        }
    };

    auto storeSmem = [&](int buf) {
        if (AHALF) {
            #pragma unroll
            for (int l = 0; l < 2; l++) {
                int fidx = tid + l * 256;
                int row = fidx >> 2, col8 = fidx & 3;
                *(uint4*)&As[buf][row][col8 * 8] = aH[l];
            }
        } else {
            #pragma unroll
            for (int l = 0; l < 4; l++) {
                int fidx = tid + l * 256;
                int row = fidx >> 3, col4 = fidx & 7;
                uint2 u;
                *(__half2*)&u.x = __floats2half2_rn(aF[l].x, aF[l].y);
                *(__half2*)&u.y = __floats2half2_rn(aF[l].z, aF[l].w);
                *(uint2*)&As[buf][row][col4 * 4] = u;
            }
        }
        #pragma unroll
        for (int l = 0; l < 2; l++) {
            int fidx = tid + l * 256;
            int row = fidx >> 4, col8 = fidx & 15;
            *(uint4*)&Bs[buf][row][col8 * 8] = bH[l];
        }
    };

    loadGlobal(0);
    storeSmem(0);
    __syncthreads();

    constexpr int NT = K / BK;
    int cur = 0;
    for (int kt = 0; kt < NT; kt++) {
        if (kt + 1 < NT) loadGlobal((kt + 1) * BK);

        #pragma unroll
        for (int ks = 0; ks < 2; ks++) {
            const int kb = ks * 16;
            uint32_t af[4][4], bf[4][2];
            #pragma unroll
            for (int mi = 0; mi < 4; mi++) {
                int row = wm0 + mi * 16 + (lane & 15);
                int col = kb + ((lane >> 4) << 3);
                ldm_x4(af[mi], smem_u32(&As[cur][row][col]));
            }
            #pragma unroll
            for (int nh = 0; nh < 2; nh++) {
                int row = kb + (lane & 15);
                int col = wn0 + nh * 16 + ((lane >> 4) << 3);
                uint32_t r[4];
                ldm_x4_t(r, smem_u32(&Bs[cur][row][col]));
                bf[nh * 2][0] = r[0]; bf[nh * 2][1] = r[1];
                bf[nh * 2 + 1][0] = r[2]; bf[nh * 2 + 1][1] = r[3];
            }
            #pragma unroll
            for (int mi = 0; mi < 4; mi++)
                #pragma unroll
                for (int ni = 0; ni < 4; ni++)
                    mma_f16(acc[mi][ni], af[mi], bf[ni]);
        }

        if (kt + 1 < NT) {
            storeSmem(cur ^ 1);
            __syncthreads();
            cur ^= 1;
        }
    }

    #pragma unroll
    for (int mi = 0; mi < 4; mi++) {
        #pragma unroll
        for (int ni = 0; ni < 4; ni++) {
            int row0 = by * BM + wm0 + mi * 16 + gid;
            int col  = bx * BN + wn0 + ni * 8 + tig * 2;
            if (row0 < M)
                *(__half2*)(C + (size_t)row0 * N + col) =
                    __floats2half2_rn(acc[mi][ni][0], acc[mi][ni][1]);
            int row1 = row0 + 8;
            if (row1 < M)
                *(__half2*)(C + (size_t)row1 * N + col) =
                    __floats2half2_rn(acc[mi][ni][2], acc[mi][ni][3]);
        }
    }
}

__global__ void __launch_bounds__(256) k_gemm_l1(const float* __restrict__ A) {
    gemm_f16_body<DHID, DIN, false>(A, g_W1h, g_Yh);
}
__global__ void __launch_bounds__(256) k_gemm_l2() {
    gemm_f16_body<DHID, DHID, true>(g_Hh, g_W2h, g_Yh);
}
__global__ void __launch_bounds__(256) k_gemm_l3() {
    gemm_f16_body<DOUT, DHID, true>(g_Hh, g_W3h, g_Y3h);
}

// ---------------------------------------------------------------------------
// Aggregation (fp16 gather, fp32 accumulate, fp16 output)
// ---------------------------------------------------------------------------

__device__ __forceinline__ void acc8(float* a, uint4 v) {
    float2 f;
    f = __half22float2(*(__half2*)&v.x); a[0] += f.x; a[1] += f.y;
    f = __half22float2(*(__half2*)&v.y); a[2] += f.x; a[3] += f.y;
    f = __half22float2(*(__half2*)&v.z); a[4] += f.x; a[5] += f.y;
    f = __half22float2(*(__half2*)&v.w); a[6] += f.x; a[7] += f.y;
}

__global__ void __launch_bounds__(128) k_agg_hid(const float* __restrict__ bias) {
    const int n    = blockIdx.x * 2 + (threadIdx.x >> 6);
    const int lane = threadIdx.x & 63;
    const int c    = lane * 8;
    const int beg  = g_rowptr[n];
    const int end  = g_rowptr[n + 1];

    float acc[8];
    #pragma unroll
    for (int q = 0; q < 8; q++) acc[q] = 0.0f;

    const uint4* Y = (const uint4*)(g_Yh);
    int i = beg;
    for (; i + 3 < end; i += 4) {
        int s0 = g_srcs[i], s1 = g_srcs[i + 1], s2 = g_srcs[i + 2], s3 = g_srcs[i + 3];
        uint4 v0 = Y[(size_t)s0 * 64 + lane];
        uint4 v1 = Y[(size_t)s1 * 64 + lane];
        uint4 v2 = Y[(size_t)s2 * 64 + lane];
        uint4 v3 = Y[(size_t)s3 * 64 + lane];
        acc8(acc, v0); acc8(acc, v1); acc8(acc, v2); acc8(acc, v3);
    }
    for (; i < end; i++) {
        uint4 v = Y[(size_t)g_srcs[i] * 64 + lane];
        acc8(acc, v);
    }

    uint4 o;
    __half2* oh = (__half2*)&o;
    #pragma unroll
    for (int q = 0; q < 4; q++) {
        float r0 = fmaxf(acc[2 * q]     + bias[c + 2 * q],     0.0f);
        float r1 = fmaxf(acc[2 * q + 1] + bias[c + 2 * q + 1], 0.0f);
        oh[q] = __floats2half2_rn(r0, r1);
    }
    *((uint4*)(g_Hh + (size_t)n * DHID + c)) = o;
}

__global__ void __launch_bounds__(128) k_agg_out(const float* __restrict__ bias) {
    const int n    = blockIdx.x * 4 + (threadIdx.x >> 5);
    const int lane = threadIdx.x & 31;
    const int c    = lane * 8;
    const int beg  = g_rowptr[n];
    const int end  = g_rowptr[n + 1];

    float acc[8];
    #pragma unroll
    for (int q = 0; q < 8; q++) acc[q] = 0.0f;

    const uint4* Y = (const uint4*)(g_Y3h);
    int i = beg;
    for (; i + 3 < end; i += 4) {
        int s0 = g_srcs[i], s1 = g_srcs[i + 1], s2 = g_srcs[i + 2], s3 = g_srcs[i + 3];
        uint4 v0 = Y[(size_t)s0 * 32 + lane];
        uint4 v1 = Y[(size_t)s1 * 32 + lane];
        uint4 v2 = Y[(size_t)s2 * 32 + lane];
        uint4 v3 = Y[(size_t)s3 * 32 + lane];
        acc8(acc, v0); acc8(acc, v1); acc8(acc, v2); acc8(acc, v3);
    }
    for (; i < end; i++) {
        uint4 v = Y[(size_t)g_srcs[i] * 32 + lane];
        acc8(acc, v);
    }

    uint4 o;
    __half2* oh = (__half2*)&o;
    #pragma unroll
    for (int q = 0; q < 4; q++)
        oh[q] = __floats2half2_rn(acc[2 * q] + bias[c + 2 * q],
                                  acc[2 * q + 1] + bias[c + 2 * q + 1]);
    *((uint4*)(g_Zh + (size_t)n * DOUT + c)) = o;
}

// ---------------------------------------------------------------------------
// Decode: 8 threads/edge, 4 interleaved uint4 per thread (deep load ILP),
// 3-step shuffle reduction within the aligned 8-lane group.
// ---------------------------------------------------------------------------

__global__ void k_decode(const int* __restrict__ eli, float* __restrict__ out) {
    int g = blockIdx.x * blockDim.x + threadIdx.x;
    int w = g >> 3;
    int lane = g & 7;
    if (w >= LL) return;

    int a = eli[w];
    int b = eli[LL + w];
    const uint4* za = (const uint4*)(g_Zh + (size_t)a * DOUT);   // 32 uint4 per row
    const uint4* zb = (const uint4*)(g_Zh + (size_t)b * DOUT);

    uint4 va[4], vb[4];
    #pragma unroll
    for (int i = 0; i < 4; i++) {
        va[i] = za[i * 8 + lane];   // lanes contiguous: 128B per chunk
        vb[i] = zb[i * 8 + lane];
    }

    float s = 0.0f;
    #pragma unroll
    for (int i = 0; i < 4; i++) {
        const __half2* ha = (const __half2*)&va[i];
        const __half2* hb = (const __half2*)&vb[i];
        #pragma unroll
        for (int q = 0; q < 4; q++) {
            float2 fa = __half22float2(ha[q]);
            float2 fb = __half22float2(hb[q]);
            s += fa.x * fb.x + fa.y * fb.y;
        }
    }

    s += __shfl_xor_sync(0xffffffffu, s, 1);
    s += __shfl_xor_sync(0xffffffffu, s, 2);
    s += __shfl_xor_sync(0xffffffffu, s, 4);
    if (lane == 0) out[w] = s;
}

// ---------------------------------------------------------------------------
// Launch: side {cvt W1, gemm1} vs main {cvt W2/W3, CSR}, then serial chain.
// ---------------------------------------------------------------------------

extern "C" void kernel_launch(void* const* d_in, const int* in_sizes, int n_in,
                              void* d_out, int out_size) {
    (void)in_sizes; (void)n_in; (void)out_size;
    const float* x   = (const float*)d_in[0];
    const int*   ei  = (const int*)  d_in[1];
    const int*   eli = (const int*)  d_in[2];
    const float* W1  = (const float*)d_in[3];
    const float* b1  = (const float*)d_in[4];
    const float* W2  = (const float*)d_in[5];
    const float* b2  = (const float*)d_in[6];
    const float* W3  = (const float*)d_in[7];
    const float* b3  = (const float*)d_in[8];
    float* out = (float*)d_out;

    const int* src = ei;
    const int* dst = ei + EE;

    static cudaStream_t s2 = nullptr;
    static cudaEvent_t evFork = nullptr, evL1 = nullptr;
    static void* d_pos_ptr = nullptr;
    if (!s2) {
        cudaStreamCreateWithFlags(&s2, cudaStreamNonBlocking);
        cudaEventCreateWithFlags(&evFork, cudaEventDisableTiming);
        cudaEventCreateWithFlags(&evL1, cudaEventDisableTiming);
        cudaGetSymbolAddress(&d_pos_ptr, g_pos);
    }

    const dim3 gHID(DHID / BN, (NN + BM - 1) / BM);
    const dim3 gOUT(DOUT / BN, (NN + BM - 1) / BM);

    // Fork: side stream converts W1 then runs layer-1 GEMM
    cudaEventRecord(evFork, 0);
    cudaStreamWaitEvent(s2, evFork, 0);
    k_cvt_w1<<<256, 256, 0, s2>>>(W1);
    k_gemm_l1<<<gHID, 256, 0, s2>>>(x);
    cudaEventRecord(evL1, s2);

    // Main stream: W2/W3 conversion + CSR build
    cudaMemsetAsync(d_pos_ptr, 0, NN * sizeof(int), 0);
    k_cvt_w23<<<384, 256>>>(W2, W3);
    k_hist<<<(EE + 255) / 256, 256>>>(dst);
    k_scan<<<1, 1024>>>();
    k_scatter<<<(EE + 255) / 256, 256>>>(src, dst);

    // Join: aggregation needs both CSR and layer-1 GEMM output
    cudaStreamWaitEvent(0, evL1, 0);

    k_agg_hid<<<NN / 2, 128>>>(b1);
    k_gemm_l2<<<gHID, 256>>>();
    k_agg_hid<<<NN / 2, 128>>>(b2);
    k_gemm_l3<<<gOUT, 256>>>();
    k_agg_out<<<NN / 4, 128>>>(b3);
    k_decode<<<(LL * 8 + 255) / 256, 256>>>(eli, out);
}